// round 3
// baseline (speedup 1.0000x reference)
#include <cuda_runtime.h>
#include <cuda.h>
#include <cuda_bf16.h>
#include <cstdint>

#define D_DIM 100000
#define W_DIM 128
#define BATCH 4096
#define G 4            // batch elements per CTA (TMA kernel)
#define BOX0 8         // inner box: 8 floats = 32 B (TMA minimum row)

// ---------------------------------------------------------------------------
// Fallback kernel (round-1): warp per batch element, 8-deep LDG gather.
// ---------------------------------------------------------------------------
__global__ __launch_bounds__(256) void sgns_kernel(
    const int* __restrict__ idx1,
    const int* __restrict__ idx2,
    const float* __restrict__ W1,
    const float* __restrict__ b1,
    const float* __restrict__ W2,
    const float* __restrict__ b2,
    float* __restrict__ out)
{
    const int warp = (blockIdx.x * blockDim.x + threadIdx.x) >> 5;
    const int lane = threadIdx.x & 31;
    if (warp >= BATCH) return;

    const long long i1 = idx1[warp];
    const long long i2 = idx2[warp];

    float a0, a1, a2, a3, c0, c1, c2, c3;
    {
        const float* p1 = W1 + (long long)lane * D_DIM + i1;
        const float* p2 = W2 + (long long)lane * D_DIM + i2;
        a0 = __ldg(p1 + 0LL * 32 * D_DIM);
        a1 = __ldg(p1 + 1LL * 32 * D_DIM);
        a2 = __ldg(p1 + 2LL * 32 * D_DIM);
        a3 = __ldg(p1 + 3LL * 32 * D_DIM);
        c0 = __ldg(p2 + 0LL * 32 * D_DIM);
        c1 = __ldg(p2 + 1LL * 32 * D_DIM);
        c2 = __ldg(p2 + 2LL * 32 * D_DIM);
        c3 = __ldg(p2 + 3LL * 32 * D_DIM);
    }

    const float e0 = b1[lane +  0], e1 = b1[lane + 32],
                e2 = b1[lane + 64], e3 = b1[lane + 96];
    const float f0 = b2[lane +  0], f1 = b2[lane + 32],
                f2 = b2[lane + 64], f3 = b2[lane + 96];

    float acc = (a0 + e0) * (c0 + f0)
              + (a1 + e1) * (c1 + f1)
              + (a2 + e2) * (c2 + f2)
              + (a3 + e3) * (c3 + f3);

    #pragma unroll
    for (int off = 16; off > 0; off >>= 1)
        acc += __shfl_xor_sync(0xFFFFFFFFu, acc, off);

    if (lane == 0) {
        const float s = 1.0f / (1.0f + expf(-acc));
        out[2 * warp + 0] = 1.0f - s;
        out[2 * warp + 1] = s;
    }
}

// ---------------------------------------------------------------------------
// TMA gather kernel: box (8,128), x aligned down to 8 floats -> each row is
// exactly one 32B sector. 128 row-requests generated per UTMALDG by the TMA
// engine, bypassing the L1tex wavefront-replay path.
// ---------------------------------------------------------------------------
__device__ __forceinline__ uint32_t smem_u32(const void* p) {
    uint32_t a;
    asm("{ .reg .u64 t; cvta.to.shared.u64 t, %1; cvt.u32.u64 %0, t; }"
        : "=r"(a) : "l"(p));
    return a;
}

__global__ __launch_bounds__(128) void sgns_tma(
    const __grid_constant__ CUtensorMap tm1,
    const __grid_constant__ CUtensorMap tm2,
    const int* __restrict__ idx1,
    const int* __restrict__ idx2,
    const float* __restrict__ b1,
    const float* __restrict__ b2,
    float* __restrict__ out)
{
    __shared__ alignas(128) float p1s[G][W_DIM][BOX0];
    __shared__ alignas(128) float p2s[G][W_DIM][BOX0];
    __shared__ alignas(8) unsigned long long mbar;

    const int tid  = threadIdx.x;
    const int lane = tid & 31;
    const int warp = tid >> 5;
    const int base = blockIdx.x * G;

    const uint32_t mbar_addr = smem_u32(&mbar);

    if (tid == 0) {
        asm volatile("mbarrier.init.shared.b64 [%0], 1;"
                     :: "r"(mbar_addr) : "memory");
    }
    __syncthreads();

    // Lanes 0..G-1 of warp 0 each issue the two column fetches for their
    // element (parallelizes the idx-load latency). tid 0 does the single
    // arrive+expect_tx; tx-count semantics make early completions safe.
    if (warp == 0 && lane < G) {
        if (lane == 0) {
            const unsigned tx_bytes = (unsigned)(G * 2 * W_DIM * BOX0 * sizeof(float));
            asm volatile("mbarrier.arrive.expect_tx.shared.b64 _, [%0], %1;"
                         :: "r"(mbar_addr), "r"(tx_bytes) : "memory");
        }
        const int x1 = idx1[base + lane] & ~(BOX0 - 1);
        const int x2 = idx2[base + lane] & ~(BOX0 - 1);
        const int y0 = 0;
        const uint32_t d1 = smem_u32(&p1s[lane][0][0]);
        const uint32_t d2 = smem_u32(&p2s[lane][0][0]);
        asm volatile(
            "cp.async.bulk.tensor.2d.shared::cta.global.tile.mbarrier::complete_tx::bytes "
            "[%0], [%1, {%2, %3}], [%4];"
            :: "r"(d1), "l"(&tm1), "r"(x1), "r"(y0), "r"(mbar_addr) : "memory");
        asm volatile(
            "cp.async.bulk.tensor.2d.shared::cta.global.tile.mbarrier::complete_tx::bytes "
            "[%0], [%1, {%2, %3}], [%4];"
            :: "r"(d2), "l"(&tm2), "r"(x2), "r"(y0), "r"(mbar_addr) : "memory");
    }

    // Wait (phase parity 0).
    {
        uint32_t done;
        asm volatile(
            "{\n\t"
            ".reg .pred p;\n\t"
            "mbarrier.try_wait.parity.acquire.cta.shared::cta.b64 p, [%1], %2;\n\t"
            "selp.b32 %0, 1, 0, p;\n\t"
            "}"
            : "=r"(done) : "r"(mbar_addr), "r"(0u) : "memory");
        if (!done) {
            asm volatile(
                "{\n\t"
                ".reg .pred P1;\n\t"
                "WAIT_LOOP_%=:\n\t"
                "mbarrier.try_wait.parity.acquire.cta.shared::cta.b64 P1, [%0], %1, 0x989680;\n\t"
                "@P1 bra.uni WAIT_DONE_%=;\n\t"
                "bra.uni WAIT_LOOP_%=;\n\t"
                "WAIT_DONE_%=:\n\t"
                "}"
                :: "r"(mbar_addr), "r"(0u) : "memory");
        }
    }

    // Compute: warp g handles batch element base+g.
    const int o1 = idx1[base + warp] & (BOX0 - 1);   // broadcast per warp
    const int o2 = idx2[base + warp] & (BOX0 - 1);

    const float e0 = b1[lane +  0], e1 = b1[lane + 32],
                e2 = b1[lane + 64], e3 = b1[lane + 96];
    const float f0 = b2[lane +  0], f1 = b2[lane + 32],
                f2 = b2[lane + 64], f3 = b2[lane + 96];

    float acc = (p1s[warp][lane +  0][o1] + e0) * (p2s[warp][lane +  0][o2] + f0)
              + (p1s[warp][lane + 32][o1] + e1) * (p2s[warp][lane + 32][o2] + f1)
              + (p1s[warp][lane + 64][o1] + e2) * (p2s[warp][lane + 64][o2] + f2)
              + (p1s[warp][lane + 96][o1] + e3) * (p2s[warp][lane + 96][o2] + f3);

    #pragma unroll
    for (int off = 16; off > 0; off >>= 1)
        acc += __shfl_xor_sync(0xFFFFFFFFu, acc, off);

    if (lane == 0) {
        const float s = 1.0f / (1.0f + expf(-acc));
        out[2 * (base + warp) + 0] = 1.0f - s;
        out[2 * (base + warp) + 1] = s;
    }
}

// ---------------------------------------------------------------------------
// Host launcher.
// ---------------------------------------------------------------------------
typedef CUresult (*EncodeTiledFn)(
    CUtensorMap*, CUtensorMapDataType, cuuint32_t, void*,
    const cuuint64_t*, const cuuint64_t*, const cuuint32_t*, const cuuint32_t*,
    CUtensorMapInterleave, CUtensorMapSwizzle, CUtensorMapL2promotion,
    CUtensorMapFloatOOBfill);

static EncodeTiledFn get_encode_fn()
{
    void* fn = nullptr;
    cudaDriverEntryPointQueryResult qres;
    if (cudaGetDriverEntryPoint("cuTensorMapEncodeTiled", &fn,
                                cudaEnableDefault, &qres) == cudaSuccess &&
        qres == cudaDriverEntryPointSuccess && fn)
        return (EncodeTiledFn)fn;
    fn = nullptr;
    if (cudaGetDriverEntryPointByVersion("cuTensorMapEncodeTiled", &fn, 12000,
                                         cudaEnableDefault, &qres) == cudaSuccess &&
        qres == cudaDriverEntryPointSuccess && fn)
        return (EncodeTiledFn)fn;
    return nullptr;
}

extern "C" void kernel_launch(void* const* d_in, const int* in_sizes, int n_in,
                              void* d_out, int out_size)
{
    const int*   idx1 = (const int*)  d_in[0];
    const int*   idx2 = (const int*)  d_in[1];
    const float* W1   = (const float*)d_in[2];
    const float* b1   = (const float*)d_in[3];
    const float* W2   = (const float*)d_in[4];
    const float* b2   = (const float*)d_in[5];
    float* out = (float*)d_out;

    EncodeTiledFn encode = get_encode_fn();
    bool ok = (encode != nullptr);

    CUtensorMap tm1, tm2;
    if (ok) {
        cuuint64_t dims[2]    = { (cuuint64_t)D_DIM, (cuuint64_t)W_DIM };
        cuuint64_t strides[1] = { (cuuint64_t)D_DIM * sizeof(float) };  // 400000 B (16B-mult)
        cuuint32_t box[2]     = { (cuuint32_t)BOX0, (cuuint32_t)W_DIM };// 32 B x 128 rows
        cuuint32_t es[2]      = { 1u, 1u };
        ok = encode(&tm1, CU_TENSOR_MAP_DATA_TYPE_FLOAT32, 2, (void*)W1,
                    dims, strides, box, es,
                    CU_TENSOR_MAP_INTERLEAVE_NONE, CU_TENSOR_MAP_SWIZZLE_NONE,
                    CU_TENSOR_MAP_L2_PROMOTION_NONE,
                    CU_TENSOR_MAP_FLOAT_OOB_FILL_NONE) == CUDA_SUCCESS;
        if (ok)
            ok = encode(&tm2, CU_TENSOR_MAP_DATA_TYPE_FLOAT32, 2, (void*)W2,
                        dims, strides, box, es,
                        CU_TENSOR_MAP_INTERLEAVE_NONE, CU_TENSOR_MAP_SWIZZLE_NONE,
                        CU_TENSOR_MAP_L2_PROMOTION_NONE,
                        CU_TENSOR_MAP_FLOAT_OOB_FILL_NONE) == CUDA_SUCCESS;
    }

    if (ok) {
        sgns_tma<<<BATCH / G, 128>>>(tm1, tm2, idx1, idx2, b1, b2, out);
    } else {
        sgns_kernel<<<BATCH / 8, 256>>>(idx1, idx2, W1, b1, W2, b2, out);
    }
}